// round 8
// baseline (speedup 1.0000x reference)
#include <cuda_runtime.h>
#include <cuda_bf16.h>
#include <cstdint>

#define NN    4096
#define CC    64
#define HH    128
#define BSDIM 48
#define NCOL  (BSDIM * CC)    // 3072

// ---------------- scratch (__device__ globals; allocation-free) -------------
__device__ float         g_d[NN];
__device__ __nv_bfloat16 g_Abf[(size_t)NN * NN];       // 33.5 MB
__device__ __nv_bfloat16 g_XdT[(size_t)NCOL * NN];     // 25 MB  [col][j], K-major

// ---------------------------------------------------------------------------
// K1 (fused): one pass over A -> rowsum/d, bf16 convert, copy to out slot 2
// ---------------------------------------------------------------------------
__global__ __launch_bounds__(256) void fuseA_kernel(const float* __restrict__ A,
                                                    float* __restrict__ Adst) {
    int row = blockIdx.x, tid = threadIdx.x;
    const float4* src = reinterpret_cast<const float4*>(A + (size_t)row * NN);
    float4* dst = reinterpret_cast<float4*>(Adst + (size_t)row * NN);
    __nv_bfloat162* ob = reinterpret_cast<__nv_bfloat162*>(g_Abf + (size_t)row * NN);
    float s = 0.f;
    #pragma unroll
    for (int it = 0; it < 4; it++) {
        int i = tid + it * 256;
        float4 v = src[i];
        dst[i] = v;
        ob[2 * i]     = __floats2bfloat162_rn(v.x, v.y);
        ob[2 * i + 1] = __floats2bfloat162_rn(v.z, v.w);
        s += (v.x + v.y) + (v.z + v.w);
    }
    __shared__ float red[8];
    #pragma unroll
    for (int o = 16; o > 0; o >>= 1) s += __shfl_down_sync(0xffffffffu, s, o);
    if ((tid & 31) == 0) red[tid >> 5] = s;
    __syncthreads();
    if (tid < 8) {
        float v = red[tid];
        #pragma unroll
        for (int o = 4; o > 0; o >>= 1) v += __shfl_down_sync(0xffu, v, o);
        if (tid == 0) g_d[row] = rsqrtf(v + 1.0f);
    }
}

// ---------------------------------------------------------------------------
// K2: XdT[bs*64+c][j] = bf16(d_j * x[bs,j,c])
// ---------------------------------------------------------------------------
__global__ __launch_bounds__(256) void build_xdt_kernel(const float* __restrict__ x) {
    __shared__ float ts[64 * 65];
    int bs = blockIdx.y, j0 = blockIdx.x * 64, tid = threadIdx.x;
    const float* xb = x + ((size_t)bs * NN + j0) * CC;
    for (int idx = tid; idx < 64 * CC; idx += 256)
        ts[(idx >> 6) * 65 + (idx & 63)] = xb[idx];
    __syncthreads();
    for (int idx = tid; idx < 64 * CC; idx += 256) {
        int c = idx >> 6, jj = idx & 63;
        int j = j0 + jj;
        g_XdT[((size_t)bs * CC + c) * NN + j] = __float2bfloat16(g_d[j] * ts[jj * 65 + c]);
    }
}

// ---------------------------------------------------------------------------
// K3 (fused GEMM + epilogue):
//   mainloop: U = Abf @ XdT^T  (bf16 mma.sync, fp32 accum), CTA 128x256
//   tail:     V = x - d*U (tf32, in smem), out = sigmoid(V @ W^T) stored direct
// grid = (NCOL/256=12, NN/128=32) = 384
// ---------------------------------------------------------------------------
#define GS      3
#define BKG     64
#define KTI     (NN / BKG)       // 64
#define ASTRIDE 72               // 64 + 8 pad (bf16 elems)
#define A_SZ    (128 * ASTRIDE)
#define B_SZ    (256 * ASTRIDE)
#define SMEM_PIPE (GS * (A_SZ + B_SZ) * 2)          // 165888 B
#define V_STR   264                                  // floats
#define W_STR   68
#define SMEM_TAIL (128 * V_STR * 4 + 128 * W_STR * 4) // 135168 + 34816 = 169984
#define SMEM_TOTAL SMEM_TAIL                          // >= SMEM_PIPE

__global__ __launch_bounds__(256, 1) void gemm_fused_kernel(const float* __restrict__ x,
                                                            const float* __restrict__ W,
                                                            float* __restrict__ out) {
    extern __shared__ __nv_bfloat16 smg[];
    uint32_t saA = (uint32_t)__cvta_generic_to_shared(smg);
    uint32_t saB = saA + GS * A_SZ * 2;

    int tid = threadIdx.x, warp = tid >> 5, lane = tid & 31;
    int rowBase = blockIdx.y * 128;
    int colBase = blockIdx.x * 256;
    int wm = warp & 1;            // M half (64 rows)
    int wn = warp >> 1;           // N quarter (64 cols) == local bs
    int bs = blockIdx.x * 4 + wn;

    float acc[4][8][4];
    #pragma unroll
    for (int a = 0; a < 4; a++)
        #pragma unroll
        for (int b = 0; b < 8; b++)
            #pragma unroll
            for (int c = 0; c < 4; c++) acc[a][b][c] = 0.f;

    auto load_stage = [&](int s, int kt) {
        int k0 = kt * BKG;
        #pragma unroll
        for (int it = 0; it < 4; it++) {          // A: 128 rows x 8 chunks
            int lin = tid + it * 256;
            int r = lin >> 3, ch = lin & 7;
            const __nv_bfloat16* src = g_Abf + (size_t)(rowBase + r) * NN + k0 + ch * 8;
            uint32_t dst = saA + (s * A_SZ + r * ASTRIDE + ch * 8) * 2;
            asm volatile("cp.async.cg.shared.global [%0],[%1],16;" :: "r"(dst), "l"(src));
        }
        #pragma unroll
        for (int it = 0; it < 8; it++) {          // B: 256 rows x 8 chunks
            int lin = tid + it * 256;
            int r = lin >> 3, ch = lin & 7;
            const __nv_bfloat16* src = g_XdT + (size_t)(colBase + r) * NN + k0 + ch * 8;
            uint32_t dst = saB + (s * B_SZ + r * ASTRIDE + ch * 8) * 2;
            asm volatile("cp.async.cg.shared.global [%0],[%1],16;" :: "r"(dst), "l"(src));
        }
        asm volatile("cp.async.commit_group;" ::);
    };

    load_stage(0, 0);
    load_stage(1, 1);

    uint32_t a[2][4][4], b[2][4][4];
    auto ldfrag = [&](int buf, uint32_t baseA, uint32_t baseB, int kk) {
        #pragma unroll
        for (int mi = 0; mi < 4; mi++) {
            uint32_t addr = baseA +
                ((wm * 64 + mi * 16 + (lane & 15)) * ASTRIDE + kk * 16 + (lane >> 4) * 8) * 2;
            asm volatile("ldmatrix.sync.aligned.m8n8.x4.shared.b16 {%0,%1,%2,%3},[%4];"
                : "=r"(a[buf][mi][0]), "=r"(a[buf][mi][1]),
                  "=r"(a[buf][mi][2]), "=r"(a[buf][mi][3]) : "r"(addr));
        }
        #pragma unroll
        for (int nj = 0; nj < 4; nj++) {
            uint32_t addr = baseB +
                ((wn * 64 + nj * 16 + (lane & 15)) * ASTRIDE + kk * 16 + (lane >> 4) * 8) * 2;
            asm volatile("ldmatrix.sync.aligned.m8n8.x4.shared.b16 {%0,%1,%2,%3},[%4];"
                : "=r"(b[buf][nj][0]), "=r"(b[buf][nj][1]),
                  "=r"(b[buf][nj][2]), "=r"(b[buf][nj][3]) : "r"(addr));
        }
    };

    int s = 0;
    for (int kt = 0; kt < KTI; kt++) {
        asm volatile("cp.async.wait_group 1;" ::);
        __syncthreads();

        int ls = s + 2; if (ls >= GS) ls -= GS;
        if (kt + 2 < KTI) load_stage(ls, kt + 2);
        else asm volatile("cp.async.commit_group;" ::);

        uint32_t baseA = saA + s * A_SZ * 2;
        uint32_t baseB = saB + s * B_SZ * 2;

        ldfrag(0, baseA, baseB, 0);
        #pragma unroll
        for (int kk = 0; kk < 4; kk++) {
            int cur = kk & 1;
            if (kk < 3) ldfrag(cur ^ 1, baseA, baseB, kk + 1);
            #pragma unroll
            for (int mi = 0; mi < 4; mi++) {
                #pragma unroll
                for (int nj = 0; nj < 4; nj++) {
                    asm volatile(
                        "mma.sync.aligned.m16n8k16.row.col.f32.bf16.bf16.f32 "
                        "{%0,%1,%2,%3},{%4,%5,%6,%7},{%8,%9},{%0,%1,%2,%3};"
                        : "+f"(acc[mi][nj*2][0]), "+f"(acc[mi][nj*2][1]),
                          "+f"(acc[mi][nj*2][2]), "+f"(acc[mi][nj*2][3])
                        : "r"(a[cur][mi][0]), "r"(a[cur][mi][1]),
                          "r"(a[cur][mi][2]), "r"(a[cur][mi][3]),
                          "r"(b[cur][nj][0]), "r"(b[cur][nj][2]));
                    asm volatile(
                        "mma.sync.aligned.m16n8k16.row.col.f32.bf16.bf16.f32 "
                        "{%0,%1,%2,%3},{%4,%5,%6,%7},{%8,%9},{%0,%1,%2,%3};"
                        : "+f"(acc[mi][nj*2+1][0]), "+f"(acc[mi][nj*2+1][1]),
                          "+f"(acc[mi][nj*2+1][2]), "+f"(acc[mi][nj*2+1][3])
                        : "r"(a[cur][mi][0]), "r"(a[cur][mi][1]),
                          "r"(a[cur][mi][2]), "r"(a[cur][mi][3]),
                          "r"(b[cur][nj][1]), "r"(b[cur][nj][3]));
                }
            }
        }
        s = s + 1 == GS ? 0 : s + 1;
    }

    // ---------------- fused epilogue tail ----------------
    __syncthreads();     // all warps done reading pipeline smem; cp.async drained
    float* sV  = reinterpret_cast<float*>(smg);           // [128][V_STR] tf32 bits
    float* sWt = sV + 128 * V_STR;                        // [128][W_STR] tf32 bits

    // stage W -> tf32 (2048 float4 loads across 256 threads)
    #pragma unroll
    for (int it = 0; it < 8; it++) {
        int lin = tid + it * 256;
        int h = lin >> 4, c4 = (lin & 15) * 4;
        float4 w = *reinterpret_cast<const float4*>(&W[h * CC + c4]);
        uint32_t t0, t1, t2, t3;
        asm volatile("cvt.rna.tf32.f32 %0,%1;" : "=r"(t0) : "f"(w.x));
        asm volatile("cvt.rna.tf32.f32 %0,%1;" : "=r"(t1) : "f"(w.y));
        asm volatile("cvt.rna.tf32.f32 %0,%1;" : "=r"(t2) : "f"(w.z));
        asm volatile("cvt.rna.tf32.f32 %0,%1;" : "=r"(t3) : "f"(w.w));
        *reinterpret_cast<float4*>(&sWt[h * W_STR + c4]) =
            make_float4(__uint_as_float(t0), __uint_as_float(t1),
                        __uint_as_float(t2), __uint_as_float(t3));
    }

    // V = x - d*U  -> tf32 in sV   (acc element (mi,nf): row wm*64+mi*16+(lane>>2)(+8),
    //                               col wn*64 + nf*8 + (lane&3)*2 (+1))
    #pragma unroll
    for (int mi = 0; mi < 4; mi++) {
        int r = wm * 64 + mi * 16 + (lane >> 2);
        float d0 = g_d[rowBase + r];
        float d1 = g_d[rowBase + r + 8];
        #pragma unroll
        for (int nf = 0; nf < 8; nf++) {
            int Cc = nf * 8 + (lane & 3) * 2;             // 0..63 within this bs
            const float* xp0 = &x[((size_t)bs * NN + rowBase + r) * CC + Cc];
            const float* xp1 = &x[((size_t)bs * NN + rowBase + r + 8) * CC + Cc];
            float2 x0 = *reinterpret_cast<const float2*>(xp0);
            float2 x1 = *reinterpret_cast<const float2*>(xp1);
            float v00 = x0.x - d0 * acc[mi][nf][0];
            float v01 = x0.y - d0 * acc[mi][nf][1];
            float v10 = x1.x - d1 * acc[mi][nf][2];
            float v11 = x1.y - d1 * acc[mi][nf][3];
            uint32_t t0, t1, t2, t3;
            asm volatile("cvt.rna.tf32.f32 %0,%1;" : "=r"(t0) : "f"(v00));
            asm volatile("cvt.rna.tf32.f32 %0,%1;" : "=r"(t1) : "f"(v01));
            asm volatile("cvt.rna.tf32.f32 %0,%1;" : "=r"(t2) : "f"(v10));
            asm volatile("cvt.rna.tf32.f32 %0,%1;" : "=r"(t3) : "f"(v11));
            sV[r * V_STR + wn * 64 + Cc]           = __uint_as_float(t0);
            sV[r * V_STR + wn * 64 + Cc + 1]       = __uint_as_float(t1);
            sV[(r + 8) * V_STR + wn * 64 + Cc]     = __uint_as_float(t2);
            sV[(r + 8) * V_STR + wn * 64 + Cc + 1] = __uint_as_float(t3);
        }
    }
    __syncthreads();

    // per-warp tf32 GEMM: out[bs, rows wm*64..+64, h 0..127] = sigmoid(V @ W^T)
    #pragma unroll
    for (int mt = 0; mt < 4; mt++) {
        float acc2[16][4];
        #pragma unroll
        for (int nt = 0; nt < 16; nt++)
            #pragma unroll
            for (int c = 0; c < 4; c++) acc2[nt][c] = 0.f;

        #pragma unroll
        for (int ks = 0; ks < 8; ks++) {
            int ar = wm * 64 + mt * 16 + (lane >> 2);
            int ac = wn * 64 + ks * 8 + (lane & 3);
            uint32_t a0 = __float_as_uint(sV[ar * V_STR + ac]);
            uint32_t a1 = __float_as_uint(sV[(ar + 8) * V_STR + ac]);
            uint32_t a2 = __float_as_uint(sV[ar * V_STR + ac + 4]);
            uint32_t a3 = __float_as_uint(sV[(ar + 8) * V_STR + ac + 4]);
            #pragma unroll
            for (int nt = 0; nt < 16; nt++) {
                int n0 = nt * 8 + (lane >> 2);
                uint32_t b0 = __float_as_uint(sWt[n0 * W_STR + ks * 8 + (lane & 3)]);
                uint32_t b1 = __float_as_uint(sWt[n0 * W_STR + ks * 8 + 4 + (lane & 3)]);
                asm volatile(
                    "mma.sync.aligned.m16n8k8.row.col.f32.tf32.tf32.f32 "
                    "{%0,%1,%2,%3},{%4,%5,%6,%7},{%8,%9},{%0,%1,%2,%3};"
                    : "+f"(acc2[nt][0]), "+f"(acc2[nt][1]),
                      "+f"(acc2[nt][2]), "+f"(acc2[nt][3])
                    : "r"(a0), "r"(a1), "r"(a2), "r"(a3), "r"(b0), "r"(b1));
            }
        }

        size_t gr = (size_t)bs * NN + rowBase + wm * 64 + mt * 16 + (lane >> 2);
        #pragma unroll
        for (int nt = 0; nt < 16; nt++) {
            int h = nt * 8 + (lane & 3) * 2;
            *reinterpret_cast<float2*>(&out[gr * HH + h]) =
                make_float2(1.0f / (1.0f + __expf(-acc2[nt][0])),
                            1.0f / (1.0f + __expf(-acc2[nt][1])));
            *reinterpret_cast<float2*>(&out[(gr + 8) * HH + h]) =
                make_float2(1.0f / (1.0f + __expf(-acc2[nt][2])),
                            1.0f / (1.0f + __expf(-acc2[nt][3])));
        }
    }
}

// ---------------------------------------------------------------------------
extern "C" void kernel_launch(void* const* d_in, const int* in_sizes, int n_in,
                              void* d_out, int out_size) {
    const float* x = (const float*)d_in[0];   // [4,12,4096,64]
    const float* A = (const float*)d_in[1];   // [4096,4096]
    const float* W = (const float*)d_in[2];   // [128,64]
    float* out = (float*)d_out;               // out [48*4096*128] then A [4096*4096]

    cudaFuncSetAttribute(gemm_fused_kernel,
                         cudaFuncAttributeMaxDynamicSharedMemorySize, SMEM_TOTAL);

    fuseA_kernel<<<NN, 256>>>(A, out + (size_t)BSDIM * NN * HH);
    build_xdt_kernel<<<dim3(NN / 64, BSDIM), 256>>>(x);
    gemm_fused_kernel<<<dim3(NCOL / 256, NN / 128), 256, SMEM_TOTAL>>>(x, W, out);
}

// round 9
// speedup vs baseline: 1.1622x; 1.1622x over previous
#include <cuda_runtime.h>
#include <cuda_bf16.h>
#include <cstdint>

#define NN    4096
#define CC    64
#define HH    128
#define BSDIM 48
#define NCOL  (BSDIM * CC)    // 3072

// ---------------- scratch (__device__ globals; allocation-free) -------------
__device__ float   g_d[NN];
__device__ float   g_S[NCOL];                       // exact colsum of Xd (fp32)
__device__ uint8_t g_Ae[(size_t)NN * NN];           // e4m3( (A-0.5)*16 )   16.8 MB
__device__ uint8_t g_Xe[(size_t)NCOL * NN];         // e4m3( 16*d_j*x )     12.6 MB, [col][j]
__device__ float   g_U[(size_t)NN * NCOL];          // (R@Xd) scaled        50 MB

__device__ __forceinline__ uint16_t pack_e4m3x2(float lo, float hi) {
    uint16_t r;
    asm volatile("cvt.rn.satfinite.e4m3x2.f32 %0, %1, %2;" : "=h"(r) : "f"(hi), "f"(lo));
    return r;   // low byte = cvt(lo), high byte = cvt(hi)
}

// ---------------------------------------------------------------------------
// K1: one pass over A -> rowsum/d, centered+scaled e4m3, copy to out slot 2.
// Blocks 0-11 also zero g_S (runs before build_xdt's atomics).
// ---------------------------------------------------------------------------
__global__ __launch_bounds__(256) void fuseA_kernel(const float* __restrict__ A,
                                                    float* __restrict__ Adst) {
    int row = blockIdx.x, tid = threadIdx.x;
    if (row < 12) g_S[row * 256 + tid] = 0.f;
    const float4* src = reinterpret_cast<const float4*>(A + (size_t)row * NN);
    float4* dst = reinterpret_cast<float4*>(Adst + (size_t)row * NN);
    uint32_t* ob = reinterpret_cast<uint32_t*>(g_Ae + (size_t)row * NN);
    float s = 0.f;
    #pragma unroll
    for (int it = 0; it < 4; it++) {
        int i = tid + it * 256;
        float4 v = src[i];
        dst[i] = v;
        uint32_t lo = pack_e4m3x2((v.x - 0.5f) * 16.f, (v.y - 0.5f) * 16.f);
        uint32_t hi = pack_e4m3x2((v.z - 0.5f) * 16.f, (v.w - 0.5f) * 16.f);
        ob[i] = lo | (hi << 16);
        s += (v.x + v.y) + (v.z + v.w);
    }
    __shared__ float red[8];
    #pragma unroll
    for (int o = 16; o > 0; o >>= 1) s += __shfl_down_sync(0xffffffffu, s, o);
    if ((tid & 31) == 0) red[tid >> 5] = s;
    __syncthreads();
    if (tid < 8) {
        float v = red[tid];
        #pragma unroll
        for (int o = 4; o > 0; o >>= 1) v += __shfl_down_sync(0xffu, v, o);
        if (tid == 0) g_d[row] = rsqrtf(v + 1.0f);
    }
}

// ---------------------------------------------------------------------------
// K2: Xe[bs*64+c][j] = e4m3(16 * d_j * x[bs,j,c]);  g_S[col] += exact fp32 sums
// grid = (NN/64, BSDIM)
// ---------------------------------------------------------------------------
__global__ __launch_bounds__(256) void build_xdt_kernel(const float* __restrict__ x) {
    __shared__ float ts[64 * 65];
    __shared__ float ds[64];
    __shared__ float colpart[4][64];
    int bs = blockIdx.y, j0 = blockIdx.x * 64, tid = threadIdx.x;
    const float* xb = x + ((size_t)bs * NN + j0) * CC;
    for (int idx = tid; idx < 64 * CC; idx += 256)
        ts[(idx >> 6) * 65 + (idx & 63)] = xb[idx];
    if (tid < 64) ds[tid] = g_d[j0 + tid];
    __syncthreads();

    // exact fp32 column partial sums (value = d_j * x)
    {
        int c = tid & 63, grp = tid >> 6;
        float p = 0.f;
        #pragma unroll
        for (int q = 0; q < 16; q++) {
            int jj = grp * 16 + q;
            p += ds[jj] * ts[jj * 65 + c];
        }
        colpart[grp][c] = p;
    }
    __syncthreads();
    if (tid < 64) {
        float s = colpart[0][tid] + colpart[1][tid] + colpart[2][tid] + colpart[3][tid];
        atomicAdd(&g_S[bs * CC + tid], s);
    }

    // quantized store (coalesced along j)
    for (int idx = tid; idx < 64 * CC; idx += 256) {
        int c = idx >> 6, jj = idx & 63;
        float v = 16.f * ds[jj] * ts[jj * 65 + c];
        uint16_t p = pack_e4m3x2(v, 0.f);
        g_Xe[((size_t)bs * CC + c) * NN + j0 + jj] = (uint8_t)(p & 0xFF);
    }
}

// ---------------------------------------------------------------------------
// K3: Uacc = R̂ @ X̂d^T  (e4m3 mma.sync m16n8k32, fp32 accum), store /256
// CTA 128x256, BK=128 fp8, 3-stage cp.async, 8 warps, warp tile 64x64
// grid = (NCOL/256=12, NN/128=32) = 384
// ---------------------------------------------------------------------------
#define GS      3
#define BKG     128                  // fp8 elems per stage
#define KTI     (NN / BKG)           // 32
#define ASTRB   144                  // bytes per row (128 + 16 pad)
#define A_ST    (128 * ASTRB)        // 18432 B
#define B_ST    (256 * ASTRB)        // 36864 B
#define SMEM_GEMM (GS * (A_ST + B_ST))   // 165888 B

__global__ __launch_bounds__(256, 1) void gemm_fp8_kernel() {
    extern __shared__ uint8_t smg[];
    uint32_t saA = (uint32_t)__cvta_generic_to_shared(smg);
    uint32_t saB = saA + GS * A_ST;

    int tid = threadIdx.x, warp = tid >> 5, lane = tid & 31;
    int rowBase = blockIdx.y * 128;
    int colBase = blockIdx.x * 256;
    int wm = warp & 1;            // M half (64 rows)
    int wn = warp >> 1;           // N quarter (64 cols)

    float acc[4][8][4];
    #pragma unroll
    for (int a = 0; a < 4; a++)
        #pragma unroll
        for (int b = 0; b < 8; b++)
            #pragma unroll
            for (int c = 0; c < 4; c++) acc[a][b][c] = 0.f;

    auto load_stage = [&](int s, int kt) {
        int k0 = kt * BKG;
        #pragma unroll
        for (int it = 0; it < 4; it++) {          // A: 128 rows x 8 chunks of 16B
            int lin = tid + it * 256;
            int r = lin >> 3, ch = lin & 7;
            const uint8_t* src = g_Ae + (size_t)(rowBase + r) * NN + k0 + ch * 16;
            uint32_t dst = saA + s * A_ST + r * ASTRB + ch * 16;
            asm volatile("cp.async.cg.shared.global [%0],[%1],16;" :: "r"(dst), "l"(src));
        }
        #pragma unroll
        for (int it = 0; it < 8; it++) {          // B: 256 rows x 8 chunks of 16B
            int lin = tid + it * 256;
            int r = lin >> 3, ch = lin & 7;
            const uint8_t* src = g_Xe + (size_t)(colBase + r) * NN + k0 + ch * 16;
            uint32_t dst = saB + s * B_ST + r * ASTRB + ch * 16;
            asm volatile("cp.async.cg.shared.global [%0],[%1],16;" :: "r"(dst), "l"(src));
        }
        asm volatile("cp.async.commit_group;" ::);
    };

    load_stage(0, 0);
    load_stage(1, 1);

    uint32_t a[2][4][4], b[2][4][4];
    auto ldfrag = [&](int buf, uint32_t baseA, uint32_t baseB, int kk) {
        #pragma unroll
        for (int mi = 0; mi < 4; mi++) {
            uint32_t addr = baseA +
                (wm * 64 + mi * 16 + (lane & 15)) * ASTRB + kk * 32 + (lane >> 4) * 16;
            asm volatile("ldmatrix.sync.aligned.m8n8.x4.shared.b16 {%0,%1,%2,%3},[%4];"
                : "=r"(a[buf][mi][0]), "=r"(a[buf][mi][1]),
                  "=r"(a[buf][mi][2]), "=r"(a[buf][mi][3]) : "r"(addr));
        }
        #pragma unroll
        for (int nj = 0; nj < 4; nj++) {
            uint32_t addr = baseB +
                (wn * 64 + nj * 16 + (lane & 15)) * ASTRB + kk * 32 + (lane >> 4) * 16;
            asm volatile("ldmatrix.sync.aligned.m8n8.x4.shared.b16 {%0,%1,%2,%3},[%4];"
                : "=r"(b[buf][nj][0]), "=r"(b[buf][nj][1]),
                  "=r"(b[buf][nj][2]), "=r"(b[buf][nj][3]) : "r"(addr));
        }
    };

    int s = 0;
    for (int kt = 0; kt < KTI; kt++) {
        asm volatile("cp.async.wait_group 1;" ::);
        __syncthreads();

        int ls = s + 2; if (ls >= GS) ls -= GS;
        if (kt + 2 < KTI) load_stage(ls, kt + 2);
        else asm volatile("cp.async.commit_group;" ::);

        uint32_t baseA = saA + s * A_ST;
        uint32_t baseB = saB + s * B_ST;

        ldfrag(0, baseA, baseB, 0);
        #pragma unroll
        for (int kk = 0; kk < 4; kk++) {          // 4 x k32 per 128-wide stage
            int cur = kk & 1;
            if (kk < 3) ldfrag(cur ^ 1, baseA, baseB, kk + 1);
            #pragma unroll
            for (int mi = 0; mi < 4; mi++) {
                #pragma unroll
                for (int nj = 0; nj < 4; nj++) {
                    asm volatile(
                        "mma.sync.aligned.m16n8k32.row.col.f32.e4m3.e4m3.f32 "
                        "{%0,%1,%2,%3},{%4,%5,%6,%7},{%8,%9},{%0,%1,%2,%3};"
                        : "+f"(acc[mi][nj*2][0]), "+f"(acc[mi][nj*2][1]),
                          "+f"(acc[mi][nj*2][2]), "+f"(acc[mi][nj*2][3])
                        : "r"(a[cur][mi][0]), "r"(a[cur][mi][1]),
                          "r"(a[cur][mi][2]), "r"(a[cur][mi][3]),
                          "r"(b[cur][nj][0]), "r"(b[cur][nj][2]));
                    asm volatile(
                        "mma.sync.aligned.m16n8k32.row.col.f32.e4m3.e4m3.f32 "
                        "{%0,%1,%2,%3},{%4,%5,%6,%7},{%8,%9},{%0,%1,%2,%3};"
                        : "+f"(acc[mi][nj*2+1][0]), "+f"(acc[mi][nj*2+1][1]),
                          "+f"(acc[mi][nj*2+1][2]), "+f"(acc[mi][nj*2+1][3])
                        : "r"(a[cur][mi][0]), "r"(a[cur][mi][1]),
                          "r"(a[cur][mi][2]), "r"(a[cur][mi][3]),
                          "r"(b[cur][nj][1]), "r"(b[cur][nj][3]));
                }
            }
        }
        s = s + 1 == GS ? 0 : s + 1;
    }

    // store U = acc / 256  (undo the 16x16 operand scaling)
    const float inv = 1.0f / 256.0f;
    #pragma unroll
    for (int mi = 0; mi < 4; mi++) {
        int r0 = rowBase + wm * 64 + mi * 16 + (lane >> 2);
        #pragma unroll
        for (int nf = 0; nf < 8; nf++) {
            int c = colBase + wn * 64 + nf * 8 + (lane & 3) * 2;
            *reinterpret_cast<float2*>(&g_U[(size_t)r0 * NCOL + c]) =
                make_float2(acc[mi][nf][0] * inv, acc[mi][nf][1] * inv);
            *reinterpret_cast<float2*>(&g_U[(size_t)(r0 + 8) * NCOL + c]) =
                make_float2(acc[mi][nf][2] * inv, acc[mi][nf][3] * inv);
        }
    }
}

// ---------------------------------------------------------------------------
// K4: out = sigmoid( (x - d*(0.5*S + U)) @ W^T )  via tf32 mma m16n8k8
// Block: 128 rows x 128 h (R7 structure)
// ---------------------------------------------------------------------------
#define EP_STR 68
#define SMEM_EPI (2 * 128 * EP_STR * 4)

__global__ __launch_bounds__(256) void epilogue_kernel(const float* __restrict__ x,
                                                       const float* __restrict__ W,
                                                       float* __restrict__ out) {
    extern __shared__ float sm[];
    float* sW = sm;
    float* sV = sm + 128 * EP_STR;
    int tid = threadIdx.x;
    int r0  = blockIdx.x * 128;
    int bs  = r0 >> 12;

    #pragma unroll
    for (int it = 0; it < 8; it++) {
        int lin = tid + it * 256;
        int h = lin >> 4, c4 = (lin & 15) * 4;
        float4 w = *reinterpret_cast<const float4*>(&W[h * CC + c4]);
        uint32_t t0, t1, t2, t3;
        asm volatile("cvt.rna.tf32.f32 %0,%1;" : "=r"(t0) : "f"(w.x));
        asm volatile("cvt.rna.tf32.f32 %0,%1;" : "=r"(t1) : "f"(w.y));
        asm volatile("cvt.rna.tf32.f32 %0,%1;" : "=r"(t2) : "f"(w.z));
        asm volatile("cvt.rna.tf32.f32 %0,%1;" : "=r"(t3) : "f"(w.w));
        *reinterpret_cast<float4*>(&sW[h * EP_STR + c4]) =
            make_float4(__uint_as_float(t0), __uint_as_float(t1),
                        __uint_as_float(t2), __uint_as_float(t3));
    }
    #pragma unroll
    for (int it = 0; it < 8; it++) {
        int lin = tid + it * 256;
        int lr = lin >> 4, c4 = (lin & 15) * 4;
        int gr = r0 + lr;
        int i  = gr & (NN - 1);
        float di = g_d[i];
        float4 xv = *reinterpret_cast<const float4*>(&x[(size_t)gr * CC + c4]);
        float4 uv = *reinterpret_cast<const float4*>(&g_U[(size_t)i * NCOL + bs * CC + c4]);
        float4 sv = *reinterpret_cast<const float4*>(&g_S[bs * CC + c4]);
        float4 v = make_float4(xv.x - di * (0.5f * sv.x + uv.x),
                               xv.y - di * (0.5f * sv.y + uv.y),
                               xv.z - di * (0.5f * sv.z + uv.z),
                               xv.w - di * (0.5f * sv.w + uv.w));
        uint32_t t0, t1, t2, t3;
        asm volatile("cvt.rna.tf32.f32 %0,%1;" : "=r"(t0) : "f"(v.x));
        asm volatile("cvt.rna.tf32.f32 %0,%1;" : "=r"(t1) : "f"(v.y));
        asm volatile("cvt.rna.tf32.f32 %0,%1;" : "=r"(t2) : "f"(v.z));
        asm volatile("cvt.rna.tf32.f32 %0,%1;" : "=r"(t3) : "f"(v.w));
        *reinterpret_cast<float4*>(&sV[lr * EP_STR + c4]) =
            make_float4(__uint_as_float(t0), __uint_as_float(t1),
                        __uint_as_float(t2), __uint_as_float(t3));
    }
    __syncthreads();

    int warp = tid >> 5, lane = tid & 31;
    int wm = warp & 3, wn = warp >> 2;

    float acc[2][8][4];
    #pragma unroll
    for (int a = 0; a < 2; a++)
        #pragma unroll
        for (int b = 0; b < 8; b++)
            #pragma unroll
            for (int c = 0; c < 4; c++) acc[a][b][c] = 0.f;

    #pragma unroll
    for (int ks = 0; ks < 8; ks++) {
        int k0 = ks * 8;
        uint32_t av[2][4];
        #pragma unroll
        for (int mi = 0; mi < 2; mi++) {
            int ar = wm * 32 + mi * 16 + (lane >> 2);
            int ac = k0 + (lane & 3);
            av[mi][0] = __float_as_uint(sV[ar * EP_STR + ac]);
            av[mi][1] = __float_as_uint(sV[(ar + 8) * EP_STR + ac]);
            av[mi][2] = __float_as_uint(sV[ar * EP_STR + ac + 4]);
            av[mi][3] = __float_as_uint(sV[(ar + 8) * EP_STR + ac + 4]);
        }
        #pragma unroll
        for (int nt = 0; nt < 8; nt++) {
            int n0 = wn * 64 + nt * 8 + (lane >> 2);
            uint32_t b0 = __float_as_uint(sW[n0 * EP_STR + k0 + (lane & 3)]);
            uint32_t b1 = __float_as_uint(sW[n0 * EP_STR + k0 + 4 + (lane & 3)]);
            #pragma unroll
            for (int mi = 0; mi < 2; mi++) {
                asm volatile(
                    "mma.sync.aligned.m16n8k8.row.col.f32.tf32.tf32.f32 "
                    "{%0,%1,%2,%3},{%4,%5,%6,%7},{%8,%9},{%0,%1,%2,%3};"
                    : "+f"(acc[mi][nt][0]), "+f"(acc[mi][nt][1]),
                      "+f"(acc[mi][nt][2]), "+f"(acc[mi][nt][3])
                    : "r"(av[mi][0]), "r"(av[mi][1]), "r"(av[mi][2]), "r"(av[mi][3]),
                      "r"(b0), "r"(b1));
            }
        }
    }

    #pragma unroll
    for (int mi = 0; mi < 2; mi++) {
        int gr = r0 + wm * 32 + mi * 16 + (lane >> 2);
        #pragma unroll
        for (int nt = 0; nt < 8; nt++) {
            int h = wn * 64 + nt * 8 + (lane & 3) * 2;
            *reinterpret_cast<float2*>(&out[(size_t)gr * HH + h]) =
                make_float2(1.0f / (1.0f + __expf(-acc[mi][nt][0])),
                            1.0f / (1.0f + __expf(-acc[mi][nt][1])));
            *reinterpret_cast<float2*>(&out[(size_t)(gr + 8) * HH + h]) =
                make_float2(1.0f / (1.0f + __expf(-acc[mi][nt][2])),
                            1.0f / (1.0f + __expf(-acc[mi][nt][3])));
        }
    }
}

// ---------------------------------------------------------------------------
extern "C" void kernel_launch(void* const* d_in, const int* in_sizes, int n_in,
                              void* d_out, int out_size) {
    const float* x = (const float*)d_in[0];   // [4,12,4096,64]
    const float* A = (const float*)d_in[1];   // [4096,4096]
    const float* W = (const float*)d_in[2];   // [128,64]
    float* out = (float*)d_out;               // out [48*4096*128] then A [4096*4096]

    cudaFuncSetAttribute(gemm_fp8_kernel,
                         cudaFuncAttributeMaxDynamicSharedMemorySize, SMEM_GEMM);
    cudaFuncSetAttribute(epilogue_kernel,
                         cudaFuncAttributeMaxDynamicSharedMemorySize, SMEM_EPI);

    fuseA_kernel<<<NN, 256>>>(A, out + (size_t)BSDIM * NN * HH);
    build_xdt_kernel<<<dim3(NN / 64, BSDIM), 256>>>(x);
    gemm_fp8_kernel<<<dim3(NCOL / 256, NN / 128), 256, SMEM_GEMM>>>();
    epilogue_kernel<<<(BSDIM * NN) / 128, 256, SMEM_EPI>>>(x, W, out);
}